// round 4
// baseline (speedup 1.0000x reference)
#include <cuda_runtime.h>
#include <cstdint>

#define HH 2048
#define WW 2048
#define NPIX (HH*WW)

#define TH 62            // output tile (62x62)
#define NB ((HH + TH - 1) / TH)   // 34 blocks per dim
// SMEM box: 64 x 64 filled (halo = output+2), padded allocation for safe
// over-reads by edge lanes/strips.
#define SROWS 66
#define SCOLS 68

// Scratch (allocation-free rule: __device__ globals)
__device__ float g_bufA[NPIX];
__device__ float g_bufB[NPIX];
__device__ float g_good[NPIX];

// ---------------- Threefry-2x32 (exact JAX semantics) ----------------
__device__ __forceinline__ uint32_t rotl32(uint32_t x, int r) {
    return __funnelshift_l(x, x, r);
}

// Add routed to the FMA pipe: mad.lo.u32 with an opaque multiplier (==1 at
// runtime, passed as kernel arg so ptxas cannot fold it to IADD3).
// Exact mod-2^32 => bit-identical to a plain add.
__device__ __forceinline__ uint32_t addf(uint32_t a, uint32_t b, uint32_t one) {
    uint32_t r;
    asm("mad.lo.u32 %0, %1, %2, %3;" : "=r"(r) : "r"(a), "r"(one), "r"(b));
    return r;
}

__device__ __forceinline__ void tf2x32(uint32_t k0, uint32_t k1,
                                       uint32_t x1in, uint32_t one,
                                       uint32_t& o0, uint32_t& o1) {
    // counter = (0, j): x0 starts as k0, x1 = j + k1
    uint32_t k2 = k0 ^ k1 ^ 0x1BD11BDAu;
    uint32_t x0 = k0;
    uint32_t x1 = addf(x1in, k1, one);
#define TF_R(rot) \
    x0 = addf(x0, x1, one); x1 = rotl32(x1, rot) ^ x0;
#define TF_R4(a,b,c,d) TF_R(a) TF_R(b) TF_R(c) TF_R(d)
    TF_R4(13,15,26,6)   x0 = addf(x0, k1, one); x1 = addf(x1, k2 + 1u, one);
    TF_R4(17,29,16,24)  x0 = addf(x0, k2, one); x1 = addf(x1, k0 + 2u, one);
    TF_R4(13,15,26,6)   x0 = addf(x0, k0, one); x1 = addf(x1, k1 + 3u, one);
    TF_R4(17,29,16,24)  x0 = addf(x0, k1, one); x1 = addf(x1, k2 + 4u, one);
    TF_R4(13,15,26,6)   x0 = addf(x0, k2, one); x1 = addf(x1, k0 + 5u, one);
#undef TF_R4
#undef TF_R
    o0 = x0; o1 = x1;
}

// Host copy for key derivation (split of key(1) into 100 keys)
static inline uint32_t h_rotl32(uint32_t x, int r) { return (x << r) | (x >> (32 - r)); }
static void h_tf2x32(uint32_t k0, uint32_t k1, uint32_t x0, uint32_t x1,
                     uint32_t& o0, uint32_t& o1) {
    uint32_t k2 = k0 ^ k1 ^ 0x1BD11BDAu;
    x0 += k0; x1 += k1;
#define TF_R4(a,b,c,d) \
    x0 += x1; x1 = h_rotl32(x1,a); x1 ^= x0; \
    x0 += x1; x1 = h_rotl32(x1,b); x1 ^= x0; \
    x0 += x1; x1 = h_rotl32(x1,c); x1 ^= x0; \
    x0 += x1; x1 = h_rotl32(x1,d); x1 ^= x0;
    TF_R4(13,15,26,6)   x0 += k1; x1 += k2 + 1u;
    TF_R4(17,29,16,24)  x0 += k2; x1 += k0 + 2u;
    TF_R4(13,15,26,6)   x0 += k0; x1 += k1 + 3u;
    TF_R4(17,29,16,24)  x0 += k1; x1 += k2 + 4u;
    TF_R4(13,15,26,6)   x0 += k2; x1 += k0 + 5u;
#undef TF_R4
    o0 = x0; o1 = x1;
}

// ---------------- Kernels ----------------
__global__ __launch_bounds__(256) void init_kernel(
    const float* __restrict__ seed, const float* __restrict__ hab,
    const float* __restrict__ ter) {
    int i = blockIdx.x * 256 + threadIdx.x;
    g_bufA[i] = seed[i] * hab[i];
    g_good[i] = fmaxf(hab[i], ter[i]);
}

// One spread step: xs = src * (0.9 + 0.1*U(key, idx)); dst = max(maxpool3x3(xs)*good, src)
// FINAL step additionally multiplies by habitat (fused epilogue).
template <bool FINAL>
__global__ __launch_bounds__(256, 5) void step_kernel(
    const float* __restrict__ src, float* __restrict__ dst,
    const float* __restrict__ good, const float* __restrict__ hab,
    uint32_t k0, uint32_t k1, uint32_t one) {
    __shared__ float xs[SROWS][SCOLS];

    const int r0 = blockIdx.y * TH;     // output tile origin
    const int c0 = blockIdx.x * TH;
    const int tid = threadIdx.x;

    // Phase 1: fill randomized 64x64 box (output tile + 1px halo) into SMEM.
    // 16 fully-unrolled iterations, shift-only indexing (no div/mod), all
    // ciphers independent -> ptxas can interleave the lat-4 chains.
    #pragma unroll
    for (int i = 0; i < 16; i++) {
        int idx = tid + i * 256;
        int rr = idx >> 6;
        int cc = idx & 63;
        int row = r0 - 1 + rr;
        int col = c0 - 1 + cc;
        float v = 0.0f;  // SAME padding: all data >= 0, so 0 == -inf here
        if ((unsigned)row < HH && (unsigned)col < WW) {
            uint32_t j = (uint32_t)((row << 11) + col);
            uint32_t o0, o1;
            tf2x32(k0, k1, j, one, o0, o1);
            uint32_t bits = o0 ^ o1;
            float u = __uint_as_float((bits >> 9) | 0x3f800000u) - 1.0f;
            float x = __ldg(&src[j]);
            v = x * (0.9f + 0.1f * u);
        }
        xs[rr][cc] = v;
    }
    __syncthreads();

    // Phase 2: separable 3x3 max, rolling vertical window of row-maxes.
    // 256 threads = 64 cols x 4 row-strips of 16 (62 valid cols/rows).
    const int oc = tid & 63;          // local out col; smem cols oc..oc+2
    const int rs = (tid >> 6) * 16;   // local out-row base

    float h0 = fmaxf(fmaxf(xs[rs    ][oc], xs[rs    ][oc+1]), xs[rs    ][oc+2]);
    float h1 = fmaxf(fmaxf(xs[rs + 1][oc], xs[rs + 1][oc+1]), xs[rs + 1][oc+2]);
    #pragma unroll
    for (int i = 0; i < 16; i++) {
        int sr = rs + i + 2;
        float h2 = fmaxf(fmaxf(xs[sr][oc], xs[sr][oc+1]), xs[sr][oc+2]);
        float m = fmaxf(fmaxf(h0, h1), h2);
        int orow = rs + i;
        int r = r0 + orow;
        int c = c0 + oc;
        if (orow < TH && oc < TH && r < HH && c < WW) {
            int g = (r << 11) + c;
            float xc = __ldg(&src[g]);
            float res = fmaxf(m * __ldg(&good[g]), xc);
            if (FINAL) res *= __ldg(&hab[g]);
            dst[g] = res;
        }
        h0 = h1; h1 = h2;
    }
}

// ---------------- Launch ----------------
extern "C" void kernel_launch(void* const* d_in, const int* in_sizes, int n_in,
                              void* d_out, int out_size) {
    (void)in_sizes; (void)n_in; (void)out_size;
    const float* seedp = (const float*)d_in[0];
    const float* habp  = (const float*)d_in[1];
    const float* terp  = (const float*)d_in[2];
    float* outp = (float*)d_out;

    float *bufA = nullptr, *bufB = nullptr, *goodp = nullptr;
    cudaGetSymbolAddress((void**)&bufA, g_bufA);
    cudaGetSymbolAddress((void**)&bufB, g_bufB);
    cudaGetSymbolAddress((void**)&goodp, g_good);

    init_kernel<<<NPIX / 256, 256>>>(seedp, habp, terp);

    // keys = jax.random.split(jax.random.key(1), 100), partitionable:
    // key_t = threefry2x32((0,1), (0,t))
    uint32_t keys[100][2];
    for (uint32_t t = 0; t < 100; t++)
        h_tf2x32(0u, 1u, 0u, t, keys[t][0], keys[t][1]);

    const uint32_t one = 1u;  // opaque to ptxas: keeps mad.lo as IMAD (fma pipe)

    dim3 grid(NB, NB);  // 34 x 34 blocks of 62x62 outputs
    const float* s = bufA;
    float* d = bufB;
    for (int t = 0; t < 99; t++) {
        step_kernel<false><<<grid, 256>>>(s, d, goodp, habp,
                                          keys[t][0], keys[t][1], one);
        const float* tmp = d;
        d = (float*)s;
        s = tmp;
    }
    // Final step: fused * habitat epilogue, writes directly to d_out.
    step_kernel<true><<<grid, 256>>>(s, outp, goodp, habp,
                                     keys[99][0], keys[99][1], one);
}

// round 6
// speedup vs baseline: 1.0972x; 1.0972x over previous
#include <cuda_runtime.h>
#include <cstdint>

#define HH 2048
#define WW 2048
#define NPIX (HH*WW)

// Output tile: 56 rows x 64 cols. Grid = 32 x 37 = 1184 = 148 SMs * 8 blocks
// -> exactly one co-resident wave at 100% theoretical occupancy (32 regs).
#define TROWS 56
#define TCOLS 64
#define GX (WW / TCOLS)                 // 32
#define GY ((HH + TROWS - 1) / TROWS)   // 37
// SMEM box: (TROWS+2) x (TCOLS+2), cols padded to 68
#define SROWS 58
#define SWID 66
#define SPITCH 68
#define SPIX (SROWS * SWID)             // 3828

// Scratch (allocation-free rule: __device__ globals)
__device__ float g_bufA[NPIX];
__device__ float g_bufB[NPIX];
__device__ float g_good[NPIX];

// ---------------- Threefry-2x32 (exact JAX semantics) ----------------
__device__ __forceinline__ uint32_t rotl32(uint32_t x, int r) {
    return __funnelshift_l(x, x, r);
}

// Add routed to the FMA pipe: mad.lo.u32 with an opaque multiplier (==1 at
// runtime, passed as kernel arg so ptxas cannot fold it to IADD3).
// Exact mod-2^32 => bit-identical to a plain add.
__device__ __forceinline__ uint32_t addf(uint32_t a, uint32_t b, uint32_t one) {
    uint32_t r;
    asm("mad.lo.u32 %0, %1, %2, %3;" : "=r"(r) : "r"(a), "r"(one), "r"(b));
    return r;
}

__device__ __forceinline__ void tf2x32(uint32_t k0, uint32_t k1,
                                       uint32_t x1in, uint32_t one,
                                       uint32_t& o0, uint32_t& o1) {
    // counter = (0, j): x0 starts as k0, x1 = j + k1
    uint32_t k2 = k0 ^ k1 ^ 0x1BD11BDAu;
    uint32_t x0 = k0;
    uint32_t x1 = addf(x1in, k1, one);
#define TF_R(rot) \
    x0 = addf(x0, x1, one); x1 = rotl32(x1, rot) ^ x0;
#define TF_R4(a,b,c,d) TF_R(a) TF_R(b) TF_R(c) TF_R(d)
    TF_R4(13,15,26,6)   x0 = addf(x0, k1, one); x1 = addf(x1, k2 + 1u, one);
    TF_R4(17,29,16,24)  x0 = addf(x0, k2, one); x1 = addf(x1, k0 + 2u, one);
    TF_R4(13,15,26,6)   x0 = addf(x0, k0, one); x1 = addf(x1, k1 + 3u, one);
    TF_R4(17,29,16,24)  x0 = addf(x0, k1, one); x1 = addf(x1, k2 + 4u, one);
    TF_R4(13,15,26,6)   x0 = addf(x0, k2, one); x1 = addf(x1, k0 + 5u, one);
#undef TF_R4
#undef TF_R
    o0 = x0; o1 = x1;
}

// Host copy for key derivation (split of key(1) into 100 keys)
static inline uint32_t h_rotl32(uint32_t x, int r) { return (x << r) | (x >> (32 - r)); }
static void h_tf2x32(uint32_t k0, uint32_t k1, uint32_t x0, uint32_t x1,
                     uint32_t& o0, uint32_t& o1) {
    uint32_t k2 = k0 ^ k1 ^ 0x1BD11BDAu;
    x0 += k0; x1 += k1;
#define TF_R4(a,b,c,d) \
    x0 += x1; x1 = h_rotl32(x1,a); x1 ^= x0; \
    x0 += x1; x1 = h_rotl32(x1,b); x1 ^= x0; \
    x0 += x1; x1 = h_rotl32(x1,c); x1 ^= x0; \
    x0 += x1; x1 = h_rotl32(x1,d); x1 ^= x0;
    TF_R4(13,15,26,6)   x0 += k1; x1 += k2 + 1u;
    TF_R4(17,29,16,24)  x0 += k2; x1 += k0 + 2u;
    TF_R4(13,15,26,6)   x0 += k0; x1 += k1 + 3u;
    TF_R4(17,29,16,24)  x0 += k1; x1 += k2 + 4u;
    TF_R4(13,15,26,6)   x0 += k2; x1 += k0 + 5u;
#undef TF_R4
    o0 = x0; o1 = x1;
}

// ---------------- Kernels ----------------
__global__ __launch_bounds__(256) void init_kernel(
    const float* __restrict__ seed, const float* __restrict__ hab,
    const float* __restrict__ ter) {
    int i = blockIdx.x * 256 + threadIdx.x;
    g_bufA[i] = seed[i] * hab[i];
    g_good[i] = fmaxf(hab[i], ter[i]);
}

// One spread step: xs = src * (0.9 + 0.1*U(key, idx)); dst = max(maxpool3x3(xs)*good, src)
// FINAL step additionally multiplies by habitat (fused epilogue).
template <bool FINAL>
__global__ __launch_bounds__(256, 8) void step_kernel(
    const float* __restrict__ src, float* __restrict__ dst,
    const float* __restrict__ good, const float* __restrict__ hab,
    uint32_t k0, uint32_t k1, uint32_t one) {
    __shared__ float xs[SROWS][SPITCH];

    const int r0 = blockIdx.y * TROWS;   // output tile origin
    const int c0 = blockIdx.x * TCOLS;
    const int tid = threadIdx.x;

    // Phase 1: fill randomized (TROWS+2)x(TCOLS+2) box into SMEM.
    // JAX partitionable threefry 32-bit bits: o0^o1 of cipher(key, (0, flat)).
    #pragma unroll
    for (int i = 0; i < 15; i++) {
        int idx = tid + i * 256;
        if (idx < SPIX) {
            int rr = idx / SWID;           // const-div -> mul/shift
            int cc = idx - rr * SWID;
            int row = r0 - 1 + rr;
            int col = c0 - 1 + cc;
            float v = 0.0f;  // SAME padding: data >= 0, so 0 == -inf here
            if ((unsigned)row < HH && (unsigned)col < WW) {
                uint32_t j = (uint32_t)((row << 11) + col);
                uint32_t o0, o1;
                tf2x32(k0, k1, j, one, o0, o1);
                uint32_t bits = o0 ^ o1;
                float u = __uint_as_float((bits >> 9) | 0x3f800000u) - 1.0f;
                float x = __ldg(&src[j]);
                v = x * (0.9f + 0.1f * u);
            }
            xs[rr][cc] = v;
        }
    }
    __syncthreads();

    // Phase 2: separable 3x3 max, rolling vertical window of row-maxes.
    // 256 threads = 64 cols x 4 row-strips of 14. All 64 cols are valid
    // outputs (tile width divides W) -> only a row guard needed.
    const int oc = tid & 63;           // output col; smem cols oc..oc+2
    const int rs = (tid >> 6) * 14;    // output-row base within tile

    float h0 = fmaxf(fmaxf(xs[rs    ][oc], xs[rs    ][oc+1]), xs[rs    ][oc+2]);
    float h1 = fmaxf(fmaxf(xs[rs + 1][oc], xs[rs + 1][oc+1]), xs[rs + 1][oc+2]);
    #pragma unroll
    for (int i = 0; i < 14; i++) {
        int sr = rs + i + 2;
        float h2 = fmaxf(fmaxf(xs[sr][oc], xs[sr][oc+1]), xs[sr][oc+2]);
        float m = fmaxf(fmaxf(h0, h1), h2);
        int r = r0 + rs + i;
        if (r < HH) {
            int g = (r << 11) + (c0 + oc);
            float xc = __ldg(&src[g]);
            float res = fmaxf(m * __ldg(&good[g]), xc);
            if (FINAL) res *= __ldg(&hab[g]);
            dst[g] = res;
        }
        h0 = h1; h1 = h2;
    }
}

// ---------------- Launch ----------------
extern "C" void kernel_launch(void* const* d_in, const int* in_sizes, int n_in,
                              void* d_out, int out_size) {
    (void)in_sizes; (void)n_in; (void)out_size;
    const float* seedp = (const float*)d_in[0];
    const float* habp  = (const float*)d_in[1];
    const float* terp  = (const float*)d_in[2];
    float* outp = (float*)d_out;

    float *bufA = nullptr, *bufB = nullptr, *goodp = nullptr;
    cudaGetSymbolAddress((void**)&bufA, g_bufA);
    cudaGetSymbolAddress((void**)&bufB, g_bufB);
    cudaGetSymbolAddress((void**)&goodp, g_good);

    init_kernel<<<NPIX / 256, 256>>>(seedp, habp, terp);

    // keys = jax.random.split(jax.random.key(1), 100), partitionable:
    // key_t = threefry2x32((0,1), (0,t))
    uint32_t keys[100][2];
    for (uint32_t t = 0; t < 100; t++)
        h_tf2x32(0u, 1u, 0u, t, keys[t][0], keys[t][1]);

    const uint32_t one = 1u;  // opaque to ptxas: keeps mad.lo as IMAD (fma pipe)

    dim3 grid(GX, GY);  // 32 x 37 = 1184 blocks = 148 SMs * 8  (single wave)
    const float* s = bufA;
    float* d = bufB;
    for (int t = 0; t < 99; t++) {
        step_kernel<false><<<grid, 256>>>(s, d, goodp, habp,
                                          keys[t][0], keys[t][1], one);
        const float* tmp = d;
        d = (float*)s;
        s = tmp;
    }
    // Final step: fused * habitat epilogue, writes directly to d_out.
    step_kernel<true><<<grid, 256>>>(s, outp, goodp, habp,
                                     keys[99][0], keys[99][1], one);
}

// round 8
// speedup vs baseline: 1.1161x; 1.0172x over previous
#include <cuda_runtime.h>
#include <cstdint>

#define HH 2048
#define WW 2048
#define NPIX (HH*WW)

// Output tile: 56 rows x 64 cols. Grid = 32 x 37 = 1184 = 148 SMs * 8 blocks
// -> exactly one co-resident wave at 100% theoretical occupancy (32 regs).
#define TROWS 56
#define TCOLS 64
#define GX (WW / TCOLS)                 // 32
#define GY ((HH + TROWS - 1) / TROWS)   // 37
// SMEM box: (TROWS+2) x (TCOLS+2) filled, padded for unguarded writes:
// 15*256 = 3840 flat indices -> max rr = 3839/66 = 58 -> need 59 rows.
#define SROWS 59
#define SWID 66
#define SPITCH 68

// Scratch (allocation-free rule: __device__ globals)
__device__ float g_bufA[NPIX];
__device__ float g_bufB[NPIX];
__device__ float g_good[NPIX];

// ---------------- Threefry-2x32 (exact JAX semantics) ----------------
// SHF-based rotate (alu pipe)
__device__ __forceinline__ uint32_t rotl32(uint32_t x, int r) {
    return __funnelshift_l(x, x, r);
}

// Add routed to the FMA pipe: mad.lo.u32 with an opaque multiplier (==1 at
// runtime, passed as kernel arg so ptxas cannot fold it to IADD3).
// Exact mod-2^32 => bit-identical to a plain add.
__device__ __forceinline__ uint32_t addf(uint32_t a, uint32_t b, uint32_t one) {
    uint32_t r;
    asm("mad.lo.u32 %0, %1, %2, %3;" : "=r"(r) : "r"(a), "r"(one), "r"(b));
    return r;
}

// IMAD-based rotate (fma pipe): x ROTL r == lo(x * 2^r) + hi(x * 2^r)
// (the two halves have disjoint bit positions, so OR == ADD; exact).
__device__ __forceinline__ uint32_t rotl_imad(uint32_t x, int r, uint32_t one) {
    uint64_t t;
    asm("mul.wide.u32 %0, %1, %2;" : "=l"(t) : "r"(x), "r"(1u << r));
    return addf((uint32_t)t, (uint32_t)(t >> 32), one);
}

__device__ __forceinline__ void tf2x32(uint32_t k0, uint32_t k1,
                                       uint32_t x1in, uint32_t one,
                                       uint32_t& o0, uint32_t& o1) {
    // counter = (0, j): x0 starts as k0, x1 = j + k1
    uint32_t k2 = k0 ^ k1 ^ 0x1BD11BDAu;
    uint32_t x0 = k0;
    uint32_t x1 = addf(x1in, k1, one);
    // Pipe-balanced rounds: 16 rotates via SHF (alu), 4 via IMAD-wide (fma)
    // -> per-cipher mix ~36 alu / ~39 fma (issue ceiling ~1.0/cyc/SMSP).
#define TF_R(rot) \
    x0 = addf(x0, x1, one); x1 = rotl32(x1, rot) ^ x0;
#define TF_RI(rot) \
    x0 = addf(x0, x1, one); x1 = rotl_imad(x1, rot, one) ^ x0;
#define TF_G(a,b,c,d) TF_R(a) TF_R(b) TF_R(c) TF_RI(d)
#define TF_G5(a,b,c,d) TF_R(a) TF_R(b) TF_R(c) TF_R(d)
    TF_G(13,15,26,6)    x0 = addf(x0, k1, one); x1 = addf(x1, k2 + 1u, one);
    TF_G(17,29,16,24)   x0 = addf(x0, k2, one); x1 = addf(x1, k0 + 2u, one);
    TF_G(13,15,26,6)    x0 = addf(x0, k0, one); x1 = addf(x1, k1 + 3u, one);
    TF_G(17,29,16,24)   x0 = addf(x0, k1, one); x1 = addf(x1, k2 + 4u, one);
    TF_G5(13,15,26,6)   x0 = addf(x0, k2, one); x1 = addf(x1, k0 + 5u, one);
#undef TF_G5
#undef TF_G
#undef TF_RI
#undef TF_R
    o0 = x0; o1 = x1;
}

// Host copy for key derivation (split of key(1) into 100 keys)
static inline uint32_t h_rotl32(uint32_t x, int r) { return (x << r) | (x >> (32 - r)); }
static void h_tf2x32(uint32_t k0, uint32_t k1, uint32_t x0, uint32_t x1,
                     uint32_t& o0, uint32_t& o1) {
    uint32_t k2 = k0 ^ k1 ^ 0x1BD11BDAu;
    x0 += k0; x1 += k1;
#define TF_R4(a,b,c,d) \
    x0 += x1; x1 = h_rotl32(x1,a); x1 ^= x0; \
    x0 += x1; x1 = h_rotl32(x1,b); x1 ^= x0; \
    x0 += x1; x1 = h_rotl32(x1,c); x1 ^= x0; \
    x0 += x1; x1 = h_rotl32(x1,d); x1 ^= x0;
    TF_R4(13,15,26,6)   x0 += k1; x1 += k2 + 1u;
    TF_R4(17,29,16,24)  x0 += k2; x1 += k0 + 2u;
    TF_R4(13,15,26,6)   x0 += k0; x1 += k1 + 3u;
    TF_R4(17,29,16,24)  x0 += k1; x1 += k2 + 4u;
    TF_R4(13,15,26,6)   x0 += k2; x1 += k0 + 5u;
#undef TF_R4
    o0 = x0; o1 = x1;
}

// ---------------- Kernels ----------------
__global__ __launch_bounds__(256) void init_kernel(
    const float* __restrict__ seed, const float* __restrict__ hab,
    const float* __restrict__ ter) {
    int i = blockIdx.x * 256 + threadIdx.x;
    g_bufA[i] = seed[i] * hab[i];
    g_good[i] = fmaxf(hab[i], ter[i]);
}

// One spread step: xs = src * (0.9 + 0.1*U(key, idx)); dst = max(maxpool3x3(xs)*good, src)
// FINAL step additionally multiplies by habitat (fused epilogue).
template <bool FINAL>
__global__ __launch_bounds__(256, 8) void step_kernel(
    const float* __restrict__ src, float* __restrict__ dst,
    const float* __restrict__ good, const float* __restrict__ hab,
    uint32_t k0, uint32_t k1, uint32_t one) {
    __shared__ float xs[SROWS][SPITCH];

    const int r0 = blockIdx.y * TROWS;   // output tile origin
    const int c0 = blockIdx.x * TCOLS;
    const int tid = threadIdx.x;

    // Phase 1: fill randomized (TROWS+2)x(TCOLS+2) box into SMEM.
    // Unguarded 15x256 sweep: spare indices land in the padding row.
    // JAX partitionable threefry 32-bit bits: o0^o1 of cipher(key, (0, flat)).
    #pragma unroll
    for (int i = 0; i < 15; i++) {
        int idx = tid + i * 256;
        int rr = idx / SWID;           // const-div -> mul/shift
        int cc = idx - rr * SWID;
        int row = r0 - 1 + rr;
        int col = c0 - 1 + cc;
        float v = 0.0f;  // SAME padding: data >= 0, so 0 == -inf here
        uint32_t j = (uint32_t)((row << 11) + col);
        uint32_t o0, o1;
        tf2x32(k0, k1, j, one, o0, o1);
        if ((unsigned)row < HH && (unsigned)col < WW) {
            uint32_t bits = o0 ^ o1;
            float u = __uint_as_float((bits >> 9) | 0x3f800000u) - 1.0f;
            float x = __ldg(&src[j]);
            v = x * (0.9f + 0.1f * u);
        }
        xs[rr][cc] = v;
    }
    __syncthreads();

    // Phase 2: separable 3x3 max, rolling vertical window of row-maxes.
    // 256 threads = 64 cols x 4 row-strips of 14. All 64 cols are valid
    // outputs (tile width divides W) -> only a row guard needed.
    const int oc = tid & 63;           // output col; smem cols oc..oc+2
    const int rs = (tid >> 6) * 14;    // output-row base within tile

    float h0 = fmaxf(fmaxf(xs[rs    ][oc], xs[rs    ][oc+1]), xs[rs    ][oc+2]);
    float h1 = fmaxf(fmaxf(xs[rs + 1][oc], xs[rs + 1][oc+1]), xs[rs + 1][oc+2]);
    #pragma unroll
    for (int i = 0; i < 14; i++) {
        int sr = rs + i + 2;
        float h2 = fmaxf(fmaxf(xs[sr][oc], xs[sr][oc+1]), xs[sr][oc+2]);
        float m = fmaxf(fmaxf(h0, h1), h2);
        int r = r0 + rs + i;
        if (r < HH) {
            int g = (r << 11) + (c0 + oc);
            float xc = __ldg(&src[g]);
            float res = fmaxf(m * __ldg(&good[g]), xc);
            if (FINAL) res *= __ldg(&hab[g]);
            dst[g] = res;
        }
        h0 = h1; h1 = h2;
    }
}

// ---------------- Launch ----------------
extern "C" void kernel_launch(void* const* d_in, const int* in_sizes, int n_in,
                              void* d_out, int out_size) {
    (void)in_sizes; (void)n_in; (void)out_size;
    const float* seedp = (const float*)d_in[0];
    const float* habp  = (const float*)d_in[1];
    const float* terp  = (const float*)d_in[2];
    float* outp = (float*)d_out;

    float *bufA = nullptr, *bufB = nullptr, *goodp = nullptr;
    cudaGetSymbolAddress((void**)&bufA, g_bufA);
    cudaGetSymbolAddress((void**)&bufB, g_bufB);
    cudaGetSymbolAddress((void**)&goodp, g_good);

    init_kernel<<<NPIX / 256, 256>>>(seedp, habp, terp);

    // keys = jax.random.split(jax.random.key(1), 100), partitionable:
    // key_t = threefry2x32((0,1), (0,t))
    uint32_t keys[100][2];
    for (uint32_t t = 0; t < 100; t++)
        h_tf2x32(0u, 1u, 0u, t, keys[t][0], keys[t][1]);

    const uint32_t one = 1u;  // opaque to ptxas: keeps mad.lo as IMAD (fma pipe)

    dim3 grid(GX, GY);  // 32 x 37 = 1184 blocks = 148 SMs * 8  (single wave)
    const float* s = bufA;
    float* d = bufB;
    for (int t = 0; t < 99; t++) {
        step_kernel<false><<<grid, 256>>>(s, d, goodp, habp,
                                          keys[t][0], keys[t][1], one);
        const float* tmp = d;
        d = (float*)s;
        s = tmp;
    }
    // Final step: fused * habitat epilogue, writes directly to d_out.
    step_kernel<true><<<grid, 256>>>(s, outp, goodp, habp,
                                     keys[99][0], keys[99][1], one);
}